// round 16
// baseline (speedup 1.0000x reference)
#include <cuda_runtime.h>
#include <cuda_bf16.h>
#include <mma.h>
using namespace nvcuda;

#define N_NODES 100000
#define M_PAD   100032            // 1563 * 64
#define N_EDGES 1600000
#define SCAN_B  1024
#define NBLK    ((N_NODES + SCAN_B - 1) / SCAN_B)   // 98

// ---------------- scratch (device globals; no runtime allocation) ----------
__device__ int   g_degi  [N_NODES];
__device__ float g_dinv  [N_NODES];
__device__ int   g_rowptr[N_NODES + 1];
__device__ int   g_cursor[N_NODES];
__device__ int   g_partial[128];
__device__ int2  g_edge[N_EDGES];                 // {src, w_bits}
__device__ float g_xw  [(size_t)M_PAD * 512];     // concat GEMM output (padded rows)
__device__ float g_bufA[(size_t)N_NODES * 64];
__device__ float g_bufB[(size_t)N_NODES * 64];
__device__ float g_bufC[(size_t)N_NODES * 64];
__device__ float g_h   [(size_t)N_NODES * 64];
__device__ __nv_bfloat16 g_xhi[(size_t)N_NODES * 128];
__device__ __nv_bfloat16 g_xlo[(size_t)N_NODES * 128];
__device__ __nv_bfloat16 g_whi[128 * 512];
__device__ __nv_bfloat16 g_wlo[128 * 512];

// ---------------- small helpers ---------------------------------------------
__global__ void k_zero2(int* __restrict__ a, int* __restrict__ b, int n) {
    int i = blockIdx.x * blockDim.x + threadIdx.x;
    if (i < n) { a[i] = 0; b[i] = 0; }
}

// ---------------- CSR build --------------------------------------------------
__global__ void k_hist(const int* __restrict__ dst, int* __restrict__ degi) {
    int e = blockIdx.x * blockDim.x + threadIdx.x;
    if (e < N_EDGES) atomicAdd(&degi[dst[e]], 1);
}

__global__ void k_dinv_k(const int* __restrict__ degi, float* __restrict__ dinv) {
    int i = blockIdx.x * blockDim.x + threadIdx.x;
    if (i < N_NODES) {
        int d = degi[i];
        dinv[i] = (d > 0) ? rsqrtf((float)d) : 0.f;
    }
}

__global__ void k_scan1(const int* __restrict__ degi, int* __restrict__ rowptr,
                        int* __restrict__ partial) {
    __shared__ int s[SCAN_B];
    int t = threadIdx.x;
    int i = blockIdx.x * SCAN_B + t;
    int v = (i < N_NODES) ? degi[i] : 0;
    s[t] = v;
    __syncthreads();
    for (int off = 1; off < SCAN_B; off <<= 1) {
        int x = (t >= off) ? s[t - off] : 0;
        __syncthreads();
        s[t] += x;
        __syncthreads();
    }
    if (i < N_NODES) rowptr[i + 1] = s[t];
    if (t == SCAN_B - 1) partial[blockIdx.x] = s[t];
}

__global__ void k_scan2(int* __restrict__ partial) {
    __shared__ int s[128];
    int t = threadIdx.x;
    int v = (t < NBLK) ? partial[t] : 0;
    s[t] = v;
    __syncthreads();
    for (int off = 1; off < 128; off <<= 1) {
        int x = (t >= off) ? s[t - off] : 0;
        __syncthreads();
        s[t] += x;
        __syncthreads();
    }
    if (t < NBLK) partial[t] = s[t] - v;   // exclusive
}

__global__ void k_scan3(int* __restrict__ rowptr, const int* __restrict__ partial) {
    int i = blockIdx.x * blockDim.x + threadIdx.x;
    if (i < N_NODES) rowptr[i + 1] += partial[i / SCAN_B];
    if (i == 0) rowptr[0] = 0;
}

__global__ void k_fill(const int* __restrict__ src, const int* __restrict__ dst,
                       const float* __restrict__ dinv, const int* __restrict__ rowptr,
                       int* __restrict__ cursor, int2* __restrict__ edge) {
    int e = blockIdx.x * blockDim.x + threadIdx.x;
    if (e >= N_EDGES) return;
    int s = src[e], d = dst[e];
    int pos = atomicAdd(&cursor[d], 1);
    int idx = rowptr[d] + pos;
    float w = -dinv[s] * dinv[d];
    edge[idx] = make_int2(s, __float_as_int(w));
}

// ---------------- bf16 hi/lo split ------------------------------------------
template<int DIN>
__global__ void __launch_bounds__(256)
k_split(const float* __restrict__ in, __nv_bfloat16* __restrict__ hi,
        __nv_bfloat16* __restrict__ lo) {
    int idx = blockIdx.x * blockDim.x + threadIdx.x;
    if (idx >= N_NODES * DIN / 4) return;
    float4 v = ((const float4*)in)[idx];
    float vs[4] = {v.x, v.y, v.z, v.w};
    __nv_bfloat16 h[4], l[4];
    #pragma unroll
    for (int q = 0; q < 4; q++) {
        h[q] = __float2bfloat16(vs[q]);
        l[q] = __float2bfloat16(vs[q] - __bfloat162float(h[q]));
    }
    __nv_bfloat162* hp = (__nv_bfloat162*)(hi + (size_t)idx * 4);
    __nv_bfloat162* lp = (__nv_bfloat162*)(lo + (size_t)idx * 4);
    hp[0] = __nv_bfloat162(h[0], h[1]); hp[1] = __nv_bfloat162(h[2], h[3]);
    lp[0] = __nv_bfloat162(l[0], l[1]); lp[1] = __nv_bfloat162(l[2], l[3]);
}

// W concat split: wsp[i][c] (c = k*DOUT + j for c < K*DOUT, 0 padded to NTP)
template<int DIN, int K, int DOUT, int NTP>
__global__ void k_wsplit(const float* __restrict__ Wb,
                         __nv_bfloat16* __restrict__ whi,
                         __nv_bfloat16* __restrict__ wlo) {
    int idx = blockIdx.x * blockDim.x + threadIdx.x;
    if (idx >= DIN * NTP) return;
    int i = idx / NTP, c = idx - i * NTP;
    float v = 0.f;
    if (c < K * DOUT)
        v = Wb[(size_t)(c / DOUT) * DIN * DOUT + (size_t)i * DOUT + (c % DOUT)];
    __nv_bfloat16 h = __float2bfloat16(v);
    whi[idx] = h;
    wlo[idx] = __float2bfloat16(v - __bfloat162float(h));
}

// ---------------- wmma split-bf16 GEMM: out[M_PAD][NTP] = X @ Wcat ----------
template<int DIN, int NTP>
__global__ void __launch_bounds__(256)
k_gemm_wmma(const __nv_bfloat16* __restrict__ Ahi, const __nv_bfloat16* __restrict__ Alo,
            const __nv_bfloat16* __restrict__ Whi, const __nv_bfloat16* __restrict__ Wlo,
            float* __restrict__ out) {
    constexpr int LDS_ = 72;
    __shared__ __align__(16) __nv_bfloat16 sAh[64][LDS_], sAl[64][LDS_];
    __shared__ __align__(16) __nv_bfloat16 sBh[64][LDS_], sBl[64][LDS_];
    int tid = threadIdx.x;
    int wid = tid >> 5;
    int m0 = blockIdx.x * 64;
    int n0 = blockIdx.y * 64;
    int wm = (wid & 3) * 16;
    int wn = (wid >> 2) * 32;

    wmma::fragment<wmma::accumulator, 16, 16, 16, float> c0, c1;
    wmma::fill_fragment(c0, 0.f);
    wmma::fill_fragment(c1, 0.f);

    for (int k0 = 0; k0 < DIN; k0 += 64) {
        {
            int r = tid >> 2, cc = (tid & 3) * 16;
            int n = m0 + r;
            uint4 vh0 = make_uint4(0u,0u,0u,0u), vh1 = vh0, vl0 = vh0, vl1 = vh0;
            if (n < N_NODES) {
                const __nv_bfloat16* ph = &Ahi[(size_t)n * DIN + k0 + cc];
                const __nv_bfloat16* pl = &Alo[(size_t)n * DIN + k0 + cc];
                vh0 = *(const uint4*)(ph);     vh1 = *(const uint4*)(ph + 8);
                vl0 = *(const uint4*)(pl);     vl1 = *(const uint4*)(pl + 8);
            }
            *(uint4*)&sAh[r][cc]     = vh0;  *(uint4*)&sAh[r][cc + 8] = vh1;
            *(uint4*)&sAl[r][cc]     = vl0;  *(uint4*)&sAl[r][cc + 8] = vl1;
        }
        for (int i = tid; i < 64 * 8; i += 256) {
            int k = i >> 3, n8 = (i & 7) * 8;
            *(uint4*)&sBh[k][n8] = *(const uint4*)&Whi[(size_t)(k0 + k) * NTP + n0 + n8];
            *(uint4*)&sBl[k][n8] = *(const uint4*)&Wlo[(size_t)(k0 + k) * NTP + n0 + n8];
        }
        __syncthreads();

        #pragma unroll
        for (int kk = 0; kk < 64; kk += 16) {
            wmma::fragment<wmma::matrix_a, 16, 16, 16, __nv_bfloat16, wmma::row_major> ah, al;
            wmma::load_matrix_sync(ah, &sAh[wm][kk], LDS_);
            wmma::load_matrix_sync(al, &sAl[wm][kk], LDS_);
            {
                wmma::fragment<wmma::matrix_b, 16, 16, 16, __nv_bfloat16, wmma::row_major> bh, bl;
                wmma::load_matrix_sync(bh, &sBh[kk][wn], LDS_);
                wmma::load_matrix_sync(bl, &sBl[kk][wn], LDS_);
                wmma::mma_sync(c0, ah, bh, c0);
                wmma::mma_sync(c0, ah, bl, c0);
                wmma::mma_sync(c0, al, bh, c0);
            }
            {
                wmma::fragment<wmma::matrix_b, 16, 16, 16, __nv_bfloat16, wmma::row_major> bh, bl;
                wmma::load_matrix_sync(bh, &sBh[kk][wn + 16], LDS_);
                wmma::load_matrix_sync(bl, &sBl[kk][wn + 16], LDS_);
                wmma::mma_sync(c1, ah, bh, c1);
                wmma::mma_sync(c1, ah, bl, c1);
                wmma::mma_sync(c1, al, bh, c1);
            }
        }
        __syncthreads();
    }

    wmma::store_matrix_sync(&out[(size_t)(m0 + wm) * NTP + n0 + wn],      c0, NTP, wmma::mem_row_major);
    wmma::store_matrix_sync(&out[(size_t)(m0 + wm) * NTP + n0 + wn + 16], c1, NTP, wmma::mem_row_major);
}

// ---------------- per-node concat GEMM for tiny layers ----------------------
template<int DIN, int K, int DOUT>
__global__ void __launch_bounds__(256)
k_gemm_node(const float* __restrict__ T, const float* __restrict__ Wb,
            float* __restrict__ out) {
    constexpr int NT = K * DOUT;
    __shared__ float sWt[DIN * NT];
    for (int idx = threadIdx.x; idx < K * DIN * DOUT; idx += blockDim.x) {
        int k = idx / (DIN * DOUT);
        int rem = idx - k * (DIN * DOUT);
        int i = rem / DOUT, j = rem - i * DOUT;
        sWt[i * NT + k * DOUT + j] = Wb[idx];
    }
    __syncthreads();
    int n = blockIdx.x * blockDim.x + threadIdx.x;
    if (n >= N_NODES) return;
    float x[DIN];
    #pragma unroll
    for (int i = 0; i < DIN; i++) x[i] = __ldg(&T[(size_t)n * DIN + i]);
    float acc[NT];
    #pragma unroll
    for (int c = 0; c < NT; c++) acc[c] = 0.f;
    #pragma unroll
    for (int i = 0; i < DIN; i++) {
        float xi = x[i];
        #pragma unroll
        for (int c = 0; c < NT; c++) acc[c] += xi * sWt[i * NT + c];
    }
    #pragma unroll
    for (int c = 0; c < NT; c++) out[(size_t)n * NT + c] = acc[c];
}

// ---------------- fused CSR prop + Clenshaw combine + epilogue --------------
// x4 unrolled edge loop over interleaved {src,w} records (R13 structure).
template<int LANES, int VEC>
__global__ void __launch_bounds__(256)
k_prop2(const int* __restrict__ rowptr, const int2* __restrict__ edge,
        const float* __restrict__ tin, int tin_stride,
        const float* __restrict__ xw, int xw_stride,
        const float* __restrict__ sub, int sub_stride,
        float* __restrict__ outp, float wscale, int mode,
        const float* __restrict__ bias,
        const float* __restrict__ bng, const float* __restrict__ bnb,
        const float* __restrict__ bnm, const float* __restrict__ bnv) {
    long long idx = (long long)blockIdx.x * blockDim.x + threadIdx.x;
    int n = (int)(idx / LANES);
    int l = (int)(idx - (long long)n * LANES);
    if (n >= N_NODES) return;
    int j0 = rowptr[n], j1 = rowptr[n + 1];
    constexpr int DIM = LANES * VEC;
    float acc[VEC];
    #pragma unroll
    for (int v = 0; v < VEC; v++) acc[v] = 0.f;

    int j = j0;
    for (; j + 4 <= j1; j += 4) {
        int2 e0 = __ldg(&edge[j]),   e1 = __ldg(&edge[j+1]);
        int2 e2 = __ldg(&edge[j+2]), e3 = __ldg(&edge[j+3]);
        float w0 = __int_as_float(e0.y), w1 = __int_as_float(e1.y);
        float w2 = __int_as_float(e2.y), w3 = __int_as_float(e3.y);
        const float* p0 = tin + (size_t)e0.x * tin_stride + l * VEC;
        const float* p1 = tin + (size_t)e1.x * tin_stride + l * VEC;
        const float* p2 = tin + (size_t)e2.x * tin_stride + l * VEC;
        const float* p3 = tin + (size_t)e3.x * tin_stride + l * VEC;
        if constexpr (VEC == 4) {
            float4 t0 = *(const float4*)p0;
            float4 t1 = *(const float4*)p1;
            float4 t2 = *(const float4*)p2;
            float4 t3 = *(const float4*)p3;
            acc[0] += w0*t0.x + w1*t1.x + w2*t2.x + w3*t3.x;
            acc[1] += w0*t0.y + w1*t1.y + w2*t2.y + w3*t3.y;
            acc[2] += w0*t0.z + w1*t1.z + w2*t2.z + w3*t3.z;
            acc[3] += w0*t0.w + w1*t1.w + w2*t2.w + w3*t3.w;
        } else if constexpr (VEC == 2) {
            float2 t0 = *(const float2*)p0;
            float2 t1 = *(const float2*)p1;
            float2 t2 = *(const float2*)p2;
            float2 t3 = *(const float2*)p3;
            acc[0] += w0*t0.x + w1*t1.x + w2*t2.x + w3*t3.x;
            acc[1] += w0*t0.y + w1*t1.y + w2*t2.y + w3*t3.y;
        } else {
            float t0 = *p0, t1 = *p1, t2 = *p2, t3 = *p3;
            acc[0] += w0*t0 + w1*t1 + w2*t2 + w3*t3;
        }
    }
    for (; j < j1; j++) {
        int2 e = __ldg(&edge[j]);
        const float* tp = tin + (size_t)e.x * tin_stride + l * VEC;
        float w = __int_as_float(e.y);
        #pragma unroll
        for (int v = 0; v < VEC; v++) acc[v] += w * tp[v];
    }

    const float* xp = xw + (size_t)n * xw_stride + l * VEC;
    const float* sp = sub ? sub + (size_t)n * sub_stride + l * VEC : nullptr;
    float* op = outp + (size_t)n * DIM + l * VEC;
    #pragma unroll
    for (int v = 0; v < VEC; v++) {
        float z = xp[v] + wscale * acc[v];
        if (sp) z -= sp[v];
        if (mode >= 1) {
            int jch = l * VEC + v;
            z += bias[jch];
            if (mode == 2) {
                z = (z - bnm[jch]) * (bng[jch] * rsqrtf(bnv[jch] + 1e-5f)) + bnb[jch];
                z = fmaxf(z, 0.f);
            }
        }
        op[v] = z;
    }
}

// ---------------- host-side layer driver (Clenshaw, tensor GEMM) ------------
template<int DIN, int DOUT, int K, int NTP, int LANES, int VEC>
static void cheb_layer(const float* input, const float* Wb, const float* bias,
                       const float* bng, const float* bnb, const float* bnm, const float* bnv,
                       float* out, int final_mode,
                       const int* rowptr, const int2* edge,
                       float* xw, float* r0, float* r1, float* r2,
                       __nv_bfloat16* xhi, __nv_bfloat16* xlo,
                       __nv_bfloat16* whi, __nv_bfloat16* wlo) {
    static_assert(LANES * VEC == DOUT, "bad LANES/VEC");

    if constexpr (DIN >= 64) {
        k_split<DIN><<<(N_NODES * DIN / 4 + 255) / 256, 256>>>(input, xhi, xlo);
        k_wsplit<DIN, K, DOUT, NTP><<<(DIN * NTP + 255) / 256, 256>>>(Wb, whi, wlo);
        dim3 grid((N_NODES + 63) / 64, NTP / 64);
        k_gemm_wmma<DIN, NTP><<<grid, 256>>>(xhi, xlo, whi, wlo, xw);
    } else {
        k_gemm_node<DIN, K, DOUT><<<(N_NODES + 255) / 256, 256>>>(input, Wb, xw);
    }
    constexpr int XWS = (DIN >= 64) ? NTP : K * DOUT;

    long long ptot = (long long)N_NODES * LANES;
    int pgrid = (int)((ptot + 255) / 256);

    const float* b1p = xw + (size_t)(K - 1) * DOUT; int b1s = XWS;
    const float* b2p = nullptr;                     int b2s = 0;
    float* rot[3] = {r0, r1, r2};
    int nx = 0;
    for (int k = K - 2; k >= 1; k--) {
        float* t = rot[nx];
        nx = (nx + 1) % 3;
        k_prop2<LANES, VEC><<<pgrid, 256>>>(rowptr, edge,
            b1p, b1s, xw + (size_t)k * DOUT, XWS, b2p, b2s,
            t, 2.f, 0, nullptr, nullptr, nullptr, nullptr, nullptr);
        b2p = b1p; b2s = b1s;
        b1p = t;   b1s = DOUT;
    }
    k_prop2<LANES, VEC><<<pgrid, 256>>>(rowptr, edge,
        b1p, b1s, xw, XWS, b2p, b2s,
        out, 1.f, final_mode, bias, bng, bnb, bnm, bnv);
}

extern "C" void kernel_launch(void* const* d_in, const int* in_sizes, int n_in,
                              void* d_out, int out_size) {
    const float* x   = (const float*)d_in[0];
    const int*   ei  = (const int*)d_in[1];
    const int*   src = ei;
    const int*   dst = ei + N_EDGES;
    const float* W1 = (const float*)d_in[2];  const float* b1 = (const float*)d_in[3];
    const float* W2 = (const float*)d_in[4];  const float* b2 = (const float*)d_in[5];
    const float* W3 = (const float*)d_in[6];  const float* b3 = (const float*)d_in[7];
    const float* W4 = (const float*)d_in[8];  const float* b4 = (const float*)d_in[9];
    const float* bn1g = (const float*)d_in[10]; const float* bn1b = (const float*)d_in[11];
    const float* bn1m = (const float*)d_in[12]; const float* bn1v = (const float*)d_in[13];
    const float* bn2g = (const float*)d_in[14]; const float* bn2b = (const float*)d_in[15];
    const float* bn2m = (const float*)d_in[16]; const float* bn2v = (const float*)d_in[17];
    const float* bn3g = (const float*)d_in[18]; const float* bn3b = (const float*)d_in[19];
    const float* bn3m = (const float*)d_in[20]; const float* bn3v = (const float*)d_in[21];

    int *degi, *rowptr, *cursor, *partial;
    int2* edge;
    float *dinv, *xw, *bufA, *bufB, *bufC, *h;
    __nv_bfloat16 *xhi, *xlo, *whi, *wlo;
    cudaGetSymbolAddress((void**)&degi,   g_degi);
    cudaGetSymbolAddress((void**)&dinv,   g_dinv);
    cudaGetSymbolAddress((void**)&rowptr, g_rowptr);
    cudaGetSymbolAddress((void**)&cursor, g_cursor);
    cudaGetSymbolAddress((void**)&partial,g_partial);
    cudaGetSymbolAddress((void**)&edge,   g_edge);
    cudaGetSymbolAddress((void**)&xw,     g_xw);
    cudaGetSymbolAddress((void**)&bufA,   g_bufA);
    cudaGetSymbolAddress((void**)&bufB,   g_bufB);
    cudaGetSymbolAddress((void**)&bufC,   g_bufC);
    cudaGetSymbolAddress((void**)&h,      g_h);
    cudaGetSymbolAddress((void**)&xhi,    g_xhi);
    cudaGetSymbolAddress((void**)&xlo,    g_xlo);
    cudaGetSymbolAddress((void**)&whi,    g_whi);
    cudaGetSymbolAddress((void**)&wlo,    g_wlo);

    // ---- CSR build ----
    k_zero2<<<(N_NODES + 255) / 256, 256>>>(degi, cursor, N_NODES);
    k_hist  <<<(N_EDGES + 255) / 256, 256>>>(dst, degi);
    k_dinv_k<<<(N_NODES + 255) / 256, 256>>>(degi, dinv);
    k_scan1 <<<NBLK, SCAN_B>>>(degi, rowptr, partial);
    k_scan2 <<<1, 128>>>(partial);
    k_scan3 <<<(N_NODES + 255) / 256, 256>>>(rowptr, partial);
    k_fill  <<<(N_EDGES + 255) / 256, 256>>>(src, dst, dinv, rowptr, cursor, edge);

    // layer 1: 128 -> 64, K=8, BN+ReLU
    cheb_layer<128, 64, 8, 512, 16, 4>(x, W1, b1, bn1g, bn1b, bn1m, bn1v, h, 2,
                                       rowptr, edge, xw, bufA, bufB, bufC,
                                       xhi, xlo, whi, wlo);
    // layer 2: 64 -> 18, K=6, BN+ReLU
    cheb_layer<64, 18, 6, 128, 9, 2>(h, W2, b2, bn2g, bn2b, bn2m, bn2v, h, 2,
                                     rowptr, edge, xw, bufA, bufB, bufC,
                                     xhi, xlo, whi, wlo);
    // layer 3: 18 -> 9, K=4, BN+ReLU
    cheb_layer<18, 9, 4, 0, 9, 1>(h, W3, b3, bn3g, bn3b, bn3m, bn3v, h, 2,
                                  rowptr, edge, xw, bufA, bufB, bufC,
                                  xhi, xlo, whi, wlo);
    // layer 4: 9 -> 10, K=4, bias only, write d_out
    cheb_layer<9, 10, 4, 0, 5, 2>(h, W4, b4, nullptr, nullptr, nullptr, nullptr,
                                  (float*)d_out, 1,
                                  rowptr, edge, xw, bufA, bufB, bufC,
                                  xhi, xlo, whi, wlo);
}

// round 17
// speedup vs baseline: 1.0288x; 1.0288x over previous
#include <cuda_runtime.h>
#include <cuda_bf16.h>
#include <mma.h>
using namespace nvcuda;

#define N_NODES 100000
#define M_PAD   100032            // 1563 * 64
#define N_EDGES 1600000
#define SCAN_B  1024
#define NBLK    ((N_NODES + SCAN_B - 1) / SCAN_B)   // 98

// ---------------- scratch (device globals; no runtime allocation) ----------
__device__ int   g_degi  [N_NODES];
__device__ float g_dinv  [N_NODES];
__device__ int   g_rowptr[N_NODES + 1];
__device__ int   g_cursor[N_NODES];
__device__ int   g_partial[128];
__device__ int   g_csrc[N_EDGES];
__device__ float g_cw  [N_EDGES];
__device__ float g_xw  [(size_t)M_PAD * 512];     // concat GEMM output (padded rows)
__device__ float g_bufA[(size_t)N_NODES * 64];
__device__ float g_bufB[(size_t)N_NODES * 64];
__device__ float g_bufC[(size_t)N_NODES * 64];
__device__ float g_h   [(size_t)N_NODES * 64];
__device__ __nv_bfloat16 g_xhi[(size_t)N_NODES * 128];
__device__ __nv_bfloat16 g_xlo[(size_t)N_NODES * 128];
__device__ __nv_bfloat16 g_whi[128 * 512];
__device__ __nv_bfloat16 g_wlo[128 * 512];

// ---------------- small helpers ---------------------------------------------
__global__ void k_zero2(int* __restrict__ a, int* __restrict__ b, int n) {
    int i = blockIdx.x * blockDim.x + threadIdx.x;
    if (i < n) { a[i] = 0; b[i] = 0; }
}

// ---------------- CSR build --------------------------------------------------
__global__ void k_hist(const int* __restrict__ dst, int* __restrict__ degi) {
    int e = blockIdx.x * blockDim.x + threadIdx.x;
    if (e < N_EDGES) atomicAdd(&degi[dst[e]], 1);
}

__global__ void k_dinv_k(const int* __restrict__ degi, float* __restrict__ dinv) {
    int i = blockIdx.x * blockDim.x + threadIdx.x;
    if (i < N_NODES) {
        int d = degi[i];
        dinv[i] = (d > 0) ? rsqrtf((float)d) : 0.f;
    }
}

__global__ void k_scan1(const int* __restrict__ degi, int* __restrict__ rowptr,
                        int* __restrict__ partial) {
    __shared__ int s[SCAN_B];
    int t = threadIdx.x;
    int i = blockIdx.x * SCAN_B + t;
    int v = (i < N_NODES) ? degi[i] : 0;
    s[t] = v;
    __syncthreads();
    for (int off = 1; off < SCAN_B; off <<= 1) {
        int x = (t >= off) ? s[t - off] : 0;
        __syncthreads();
        s[t] += x;
        __syncthreads();
    }
    if (i < N_NODES) rowptr[i + 1] = s[t];
    if (t == SCAN_B - 1) partial[blockIdx.x] = s[t];
}

__global__ void k_scan2(int* __restrict__ partial) {
    __shared__ int s[128];
    int t = threadIdx.x;
    int v = (t < NBLK) ? partial[t] : 0;
    s[t] = v;
    __syncthreads();
    for (int off = 1; off < 128; off <<= 1) {
        int x = (t >= off) ? s[t - off] : 0;
        __syncthreads();
        s[t] += x;
        __syncthreads();
    }
    if (t < NBLK) partial[t] = s[t] - v;   // exclusive
}

__global__ void k_scan3(int* __restrict__ rowptr, const int* __restrict__ partial) {
    int i = blockIdx.x * blockDim.x + threadIdx.x;
    if (i < N_NODES) rowptr[i + 1] += partial[i / SCAN_B];
    if (i == 0) rowptr[0] = 0;
}

__global__ void k_fill(const int* __restrict__ src, const int* __restrict__ dst,
                       const float* __restrict__ dinv, const int* __restrict__ rowptr,
                       int* __restrict__ cursor, int* __restrict__ csrc,
                       float* __restrict__ cw) {
    int e = blockIdx.x * blockDim.x + threadIdx.x;
    if (e >= N_EDGES) return;
    int s = src[e], d = dst[e];
    int pos = atomicAdd(&cursor[d], 1);
    int idx = rowptr[d] + pos;
    csrc[idx] = s;
    cw[idx]   = -dinv[s] * dinv[d];
}

// ---------------- bf16 hi/lo split ------------------------------------------
template<int DIN>
__global__ void __launch_bounds__(256)
k_split(const float* __restrict__ in, __nv_bfloat16* __restrict__ hi,
        __nv_bfloat16* __restrict__ lo) {
    int idx = blockIdx.x * blockDim.x + threadIdx.x;
    if (idx >= N_NODES * DIN / 4) return;
    float4 v = ((const float4*)in)[idx];
    float vs[4] = {v.x, v.y, v.z, v.w};
    __nv_bfloat16 h[4], l[4];
    #pragma unroll
    for (int q = 0; q < 4; q++) {
        h[q] = __float2bfloat16(vs[q]);
        l[q] = __float2bfloat16(vs[q] - __bfloat162float(h[q]));
    }
    __nv_bfloat162* hp = (__nv_bfloat162*)(hi + (size_t)idx * 4);
    __nv_bfloat162* lp = (__nv_bfloat162*)(lo + (size_t)idx * 4);
    hp[0] = __nv_bfloat162(h[0], h[1]); hp[1] = __nv_bfloat162(h[2], h[3]);
    lp[0] = __nv_bfloat162(l[0], l[1]); lp[1] = __nv_bfloat162(l[2], l[3]);
}

// W concat split: wsp[i][c] (c = k*DOUT + j for c < K*DOUT, 0 padded to NTP)
template<int DIN, int K, int DOUT, int NTP>
__global__ void k_wsplit(const float* __restrict__ Wb,
                         __nv_bfloat16* __restrict__ whi,
                         __nv_bfloat16* __restrict__ wlo) {
    int idx = blockIdx.x * blockDim.x + threadIdx.x;
    if (idx >= DIN * NTP) return;
    int i = idx / NTP, c = idx - i * NTP;
    float v = 0.f;
    if (c < K * DOUT)
        v = Wb[(size_t)(c / DOUT) * DIN * DOUT + (size_t)i * DOUT + (c % DOUT)];
    __nv_bfloat16 h = __float2bfloat16(v);
    whi[idx] = h;
    wlo[idx] = __float2bfloat16(v - __bfloat162float(h));
}

// ---------------- wmma split-bf16 GEMM: out[M_PAD][NTP] = X @ Wcat ----------
template<int DIN, int NTP>
__global__ void __launch_bounds__(256)
k_gemm_wmma(const __nv_bfloat16* __restrict__ Ahi, const __nv_bfloat16* __restrict__ Alo,
            const __nv_bfloat16* __restrict__ Whi, const __nv_bfloat16* __restrict__ Wlo,
            float* __restrict__ out) {
    constexpr int LDS_ = 72;
    __shared__ __align__(16) __nv_bfloat16 sAh[64][LDS_], sAl[64][LDS_];
    __shared__ __align__(16) __nv_bfloat16 sBh[64][LDS_], sBl[64][LDS_];
    int tid = threadIdx.x;
    int wid = tid >> 5;
    int m0 = blockIdx.x * 64;
    int n0 = blockIdx.y * 64;
    int wm = (wid & 3) * 16;
    int wn = (wid >> 2) * 32;

    wmma::fragment<wmma::accumulator, 16, 16, 16, float> c0, c1;
    wmma::fill_fragment(c0, 0.f);
    wmma::fill_fragment(c1, 0.f);

    for (int k0 = 0; k0 < DIN; k0 += 64) {
        {
            int r = tid >> 2, cc = (tid & 3) * 16;
            int n = m0 + r;
            uint4 vh0 = make_uint4(0u,0u,0u,0u), vh1 = vh0, vl0 = vh0, vl1 = vh0;
            if (n < N_NODES) {
                const __nv_bfloat16* ph = &Ahi[(size_t)n * DIN + k0 + cc];
                const __nv_bfloat16* pl = &Alo[(size_t)n * DIN + k0 + cc];
                vh0 = *(const uint4*)(ph);     vh1 = *(const uint4*)(ph + 8);
                vl0 = *(const uint4*)(pl);     vl1 = *(const uint4*)(pl + 8);
            }
            *(uint4*)&sAh[r][cc]     = vh0;  *(uint4*)&sAh[r][cc + 8] = vh1;
            *(uint4*)&sAl[r][cc]     = vl0;  *(uint4*)&sAl[r][cc + 8] = vl1;
        }
        for (int i = tid; i < 64 * 8; i += 256) {
            int k = i >> 3, n8 = (i & 7) * 8;
            *(uint4*)&sBh[k][n8] = *(const uint4*)&Whi[(size_t)(k0 + k) * NTP + n0 + n8];
            *(uint4*)&sBl[k][n8] = *(const uint4*)&Wlo[(size_t)(k0 + k) * NTP + n0 + n8];
        }
        __syncthreads();

        #pragma unroll
        for (int kk = 0; kk < 64; kk += 16) {
            wmma::fragment<wmma::matrix_a, 16, 16, 16, __nv_bfloat16, wmma::row_major> ah, al;
            wmma::load_matrix_sync(ah, &sAh[wm][kk], LDS_);
            wmma::load_matrix_sync(al, &sAl[wm][kk], LDS_);
            {
                wmma::fragment<wmma::matrix_b, 16, 16, 16, __nv_bfloat16, wmma::row_major> bh, bl;
                wmma::load_matrix_sync(bh, &sBh[kk][wn], LDS_);
                wmma::load_matrix_sync(bl, &sBl[kk][wn], LDS_);
                wmma::mma_sync(c0, ah, bh, c0);
                wmma::mma_sync(c0, ah, bl, c0);
                wmma::mma_sync(c0, al, bh, c0);
            }
            {
                wmma::fragment<wmma::matrix_b, 16, 16, 16, __nv_bfloat16, wmma::row_major> bh, bl;
                wmma::load_matrix_sync(bh, &sBh[kk][wn + 16], LDS_);
                wmma::load_matrix_sync(bl, &sBl[kk][wn + 16], LDS_);
                wmma::mma_sync(c1, ah, bh, c1);
                wmma::mma_sync(c1, ah, bl, c1);
                wmma::mma_sync(c1, al, bh, c1);
            }
        }
        __syncthreads();
    }

    wmma::store_matrix_sync(&out[(size_t)(m0 + wm) * NTP + n0 + wn],      c0, NTP, wmma::mem_row_major);
    wmma::store_matrix_sync(&out[(size_t)(m0 + wm) * NTP + n0 + wn + 16], c1, NTP, wmma::mem_row_major);
}

// ---------------- per-node concat GEMM for tiny layers ----------------------
template<int DIN, int K, int DOUT>
__global__ void __launch_bounds__(256)
k_gemm_node(const float* __restrict__ T, const float* __restrict__ Wb,
            float* __restrict__ out) {
    constexpr int NT = K * DOUT;
    __shared__ float sWt[DIN * NT];
    for (int idx = threadIdx.x; idx < K * DIN * DOUT; idx += blockDim.x) {
        int k = idx / (DIN * DOUT);
        int rem = idx - k * (DIN * DOUT);
        int i = rem / DOUT, j = rem - i * DOUT;
        sWt[i * NT + k * DOUT + j] = Wb[idx];
    }
    __syncthreads();
    int n = blockIdx.x * blockDim.x + threadIdx.x;
    if (n >= N_NODES) return;
    float x[DIN];
    #pragma unroll
    for (int i = 0; i < DIN; i++) x[i] = __ldg(&T[(size_t)n * DIN + i]);
    float acc[NT];
    #pragma unroll
    for (int c = 0; c < NT; c++) acc[c] = 0.f;
    #pragma unroll
    for (int i = 0; i < DIN; i++) {
        float xi = x[i];
        #pragma unroll
        for (int c = 0; c < NT; c++) acc[c] += xi * sWt[i * NT + c];
    }
    #pragma unroll
    for (int c = 0; c < NT; c++) out[(size_t)n * NT + c] = acc[c];
}

// ---------------- fused CSR prop + Clenshaw combine + epilogue --------------
// x4 unrolled edge loop (R13 structure), separate csrc/cw streams.
// Optional fused bf16 hi/lo output for the next layer's tensor GEMM.
template<int LANES, int VEC>
__global__ void __launch_bounds__(256)
k_prop2(const int* __restrict__ rowptr, const int* __restrict__ csrc,
        const float* __restrict__ cw,
        const float* __restrict__ tin, int tin_stride,
        const float* __restrict__ xw, int xw_stride,
        const float* __restrict__ sub, int sub_stride,
        float* __restrict__ outp, float wscale, int mode,
        const float* __restrict__ bias,
        const float* __restrict__ bng, const float* __restrict__ bnb,
        const float* __restrict__ bnm, const float* __restrict__ bnv,
        __nv_bfloat16* __restrict__ ohi, __nv_bfloat16* __restrict__ olo) {
    long long idx = (long long)blockIdx.x * blockDim.x + threadIdx.x;
    int n = (int)(idx / LANES);
    int l = (int)(idx - (long long)n * LANES);
    if (n >= N_NODES) return;
    int j0 = rowptr[n], j1 = rowptr[n + 1];
    constexpr int DIM = LANES * VEC;
    float acc[VEC];
    #pragma unroll
    for (int v = 0; v < VEC; v++) acc[v] = 0.f;

    int j = j0;
    for (; j + 4 <= j1; j += 4) {
        int   s0 = __ldg(&csrc[j]),   s1 = __ldg(&csrc[j+1]);
        int   s2 = __ldg(&csrc[j+2]), s3 = __ldg(&csrc[j+3]);
        float w0 = __ldg(&cw[j]),     w1 = __ldg(&cw[j+1]);
        float w2 = __ldg(&cw[j+2]),   w3 = __ldg(&cw[j+3]);
        const float* p0 = tin + (size_t)s0 * tin_stride + l * VEC;
        const float* p1 = tin + (size_t)s1 * tin_stride + l * VEC;
        const float* p2 = tin + (size_t)s2 * tin_stride + l * VEC;
        const float* p3 = tin + (size_t)s3 * tin_stride + l * VEC;
        if constexpr (VEC == 4) {
            float4 t0 = *(const float4*)p0;
            float4 t1 = *(const float4*)p1;
            float4 t2 = *(const float4*)p2;
            float4 t3 = *(const float4*)p3;
            acc[0] += w0*t0.x + w1*t1.x + w2*t2.x + w3*t3.x;
            acc[1] += w0*t0.y + w1*t1.y + w2*t2.y + w3*t3.y;
            acc[2] += w0*t0.z + w1*t1.z + w2*t2.z + w3*t3.z;
            acc[3] += w0*t0.w + w1*t1.w + w2*t2.w + w3*t3.w;
        } else if constexpr (VEC == 2) {
            float2 t0 = *(const float2*)p0;
            float2 t1 = *(const float2*)p1;
            float2 t2 = *(const float2*)p2;
            float2 t3 = *(const float2*)p3;
            acc[0] += w0*t0.x + w1*t1.x + w2*t2.x + w3*t3.x;
            acc[1] += w0*t0.y + w1*t1.y + w2*t2.y + w3*t3.y;
        } else {
            float t0 = *p0, t1 = *p1, t2 = *p2, t3 = *p3;
            acc[0] += w0*t0 + w1*t1 + w2*t2 + w3*t3;
        }
    }
    for (; j < j1; j++) {
        int s   = __ldg(&csrc[j]);
        float w = __ldg(&cw[j]);
        const float* tp = tin + (size_t)s * tin_stride + l * VEC;
        #pragma unroll
        for (int v = 0; v < VEC; v++) acc[v] += w * tp[v];
    }

    const float* xp = xw + (size_t)n * xw_stride + l * VEC;
    const float* sp = sub ? sub + (size_t)n * sub_stride + l * VEC : nullptr;
    float* op = outp + (size_t)n * DIM + l * VEC;
    #pragma unroll
    for (int v = 0; v < VEC; v++) {
        float z = xp[v] + wscale * acc[v];
        if (sp) z -= sp[v];
        if (mode >= 1) {
            int jch = l * VEC + v;
            z += bias[jch];
            if (mode == 2) {
                z = (z - bnm[jch]) * (bng[jch] * rsqrtf(bnv[jch] + 1e-5f)) + bnb[jch];
                z = fmaxf(z, 0.f);
            }
        }
        op[v] = z;
        if (ohi) {
            __nv_bfloat16 hh = __float2bfloat16(z);
            ohi[(size_t)n * DIM + l * VEC + v] = hh;
            olo[(size_t)n * DIM + l * VEC + v] =
                __float2bfloat16(z - __bfloat162float(hh));
        }
    }
}

// ---------------- host-side layer driver (Clenshaw, tensor GEMM) ------------
template<int DIN, int DOUT, int K, int NTP, int LANES, int VEC>
static void cheb_layer(const float* input, const float* Wb, const float* bias,
                       const float* bng, const float* bnb, const float* bnm, const float* bnv,
                       float* out, int final_mode,
                       const int* rowptr, const int* csrc, const float* cw,
                       float* xw, float* r0, float* r1, float* r2,
                       __nv_bfloat16* xhi, __nv_bfloat16* xlo,
                       __nv_bfloat16* whi, __nv_bfloat16* wlo,
                       bool do_split,                      // split input -> xhi/xlo
                       __nv_bfloat16* ohi, __nv_bfloat16* olo) {  // fused split out
    static_assert(LANES * VEC == DOUT, "bad LANES/VEC");

    if constexpr (DIN >= 64) {
        if (do_split)
            k_split<DIN><<<(N_NODES * DIN / 4 + 255) / 256, 256>>>(input, xhi, xlo);
        k_wsplit<DIN, K, DOUT, NTP><<<(DIN * NTP + 255) / 256, 256>>>(Wb, whi, wlo);
        dim3 grid((N_NODES + 63) / 64, NTP / 64);
        k_gemm_wmma<DIN, NTP><<<grid, 256>>>(xhi, xlo, whi, wlo, xw);
    } else {
        k_gemm_node<DIN, K, DOUT><<<(N_NODES + 255) / 256, 256>>>(input, Wb, xw);
    }
    constexpr int XWS = (DIN >= 64) ? NTP : K * DOUT;

    long long ptot = (long long)N_NODES * LANES;
    int pgrid = (int)((ptot + 255) / 256);

    const float* b1p = xw + (size_t)(K - 1) * DOUT; int b1s = XWS;
    const float* b2p = nullptr;                     int b2s = 0;
    float* rot[3] = {r0, r1, r2};
    int nx = 0;
    for (int k = K - 2; k >= 1; k--) {
        float* t = rot[nx];
        nx = (nx + 1) % 3;
        k_prop2<LANES, VEC><<<pgrid, 256>>>(rowptr, csrc, cw,
            b1p, b1s, xw + (size_t)k * DOUT, XWS, b2p, b2s,
            t, 2.f, 0, nullptr, nullptr, nullptr, nullptr, nullptr,
            nullptr, nullptr);
        b2p = b1p; b2s = b1s;
        b1p = t;   b1s = DOUT;
    }
    k_prop2<LANES, VEC><<<pgrid, 256>>>(rowptr, csrc, cw,
        b1p, b1s, xw, XWS, b2p, b2s,
        out, 1.f, final_mode, bias, bng, bnb, bnm, bnv,
        ohi, olo);
}

extern "C" void kernel_launch(void* const* d_in, const int* in_sizes, int n_in,
                              void* d_out, int out_size) {
    const float* x   = (const float*)d_in[0];
    const int*   ei  = (const int*)d_in[1];
    const int*   src = ei;
    const int*   dst = ei + N_EDGES;
    const float* W1 = (const float*)d_in[2];  const float* b1 = (const float*)d_in[3];
    const float* W2 = (const float*)d_in[4];  const float* b2 = (const float*)d_in[5];
    const float* W3 = (const float*)d_in[6];  const float* b3 = (const float*)d_in[7];
    const float* W4 = (const float*)d_in[8];  const float* b4 = (const float*)d_in[9];
    const float* bn1g = (const float*)d_in[10]; const float* bn1b = (const float*)d_in[11];
    const float* bn1m = (const float*)d_in[12]; const float* bn1v = (const float*)d_in[13];
    const float* bn2g = (const float*)d_in[14]; const float* bn2b = (const float*)d_in[15];
    const float* bn2m = (const float*)d_in[16]; const float* bn2v = (const float*)d_in[17];
    const float* bn3g = (const float*)d_in[18]; const float* bn3b = (const float*)d_in[19];
    const float* bn3m = (const float*)d_in[20]; const float* bn3v = (const float*)d_in[21];

    int *degi, *rowptr, *cursor, *partial, *csrc;
    float *dinv, *cw, *xw, *bufA, *bufB, *bufC, *h;
    __nv_bfloat16 *xhi, *xlo, *whi, *wlo;
    cudaGetSymbolAddress((void**)&degi,   g_degi);
    cudaGetSymbolAddress((void**)&dinv,   g_dinv);
    cudaGetSymbolAddress((void**)&rowptr, g_rowptr);
    cudaGetSymbolAddress((void**)&cursor, g_cursor);
    cudaGetSymbolAddress((void**)&partial,g_partial);
    cudaGetSymbolAddress((void**)&csrc,   g_csrc);
    cudaGetSymbolAddress((void**)&cw,     g_cw);
    cudaGetSymbolAddress((void**)&xw,     g_xw);
    cudaGetSymbolAddress((void**)&bufA,   g_bufA);
    cudaGetSymbolAddress((void**)&bufB,   g_bufB);
    cudaGetSymbolAddress((void**)&bufC,   g_bufC);
    cudaGetSymbolAddress((void**)&h,      g_h);
    cudaGetSymbolAddress((void**)&xhi,    g_xhi);
    cudaGetSymbolAddress((void**)&xlo,    g_xlo);
    cudaGetSymbolAddress((void**)&whi,    g_whi);
    cudaGetSymbolAddress((void**)&wlo,    g_wlo);

    // ---- CSR build ----
    k_zero2<<<(N_NODES + 255) / 256, 256>>>(degi, cursor, N_NODES);
    k_hist  <<<(N_EDGES + 255) / 256, 256>>>(dst, degi);
    k_dinv_k<<<(N_NODES + 255) / 256, 256>>>(degi, dinv);
    k_scan1 <<<NBLK, SCAN_B>>>(degi, rowptr, partial);
    k_scan2 <<<1, 128>>>(partial);
    k_scan3 <<<(N_NODES + 255) / 256, 256>>>(rowptr, partial);
    k_fill  <<<(N_EDGES + 255) / 256, 256>>>(src, dst, dinv, rowptr, cursor, csrc, cw);

    // layer 1: 128 -> 64, K=8, BN+ReLU; fused bf16 split of h for layer 2
    cheb_layer<128, 64, 8, 512, 16, 4>(x, W1, b1, bn1g, bn1b, bn1m, bn1v, h, 2,
                                       rowptr, csrc, cw, xw, bufA, bufB, bufC,
                                       xhi, xlo, whi, wlo,
                                       true, xhi, xlo);
    // layer 2: 64 -> 18, K=6, BN+ReLU (xhi/xlo already written at stride 64)
    cheb_layer<64, 18, 6, 128, 9, 2>(h, W2, b2, bn2g, bn2b, bn2m, bn2v, h, 2,
                                     rowptr, csrc, cw, xw, bufA, bufB, bufC,
                                     xhi, xlo, whi, wlo,
                                     false, nullptr, nullptr);
    // layer 3: 18 -> 9, K=4, BN+ReLU
    cheb_layer<18, 9, 4, 0, 9, 1>(h, W3, b3, bn3g, bn3b, bn3m, bn3v, h, 2,
                                  rowptr, csrc, cw, xw, bufA, bufB, bufC,
                                  xhi, xlo, whi, wlo,
                                  false, nullptr, nullptr);
    // layer 4: 9 -> 10, K=4, bias only, write d_out
    cheb_layer<9, 10, 4, 0, 5, 2>(h, W4, b4, nullptr, nullptr, nullptr, nullptr,
                                  (float*)d_out, 1,
                                  rowptr, csrc, cw, xw, bufA, bufB, bufC,
                                  xhi, xlo, whi, wlo,
                                  false, nullptr, nullptr);
}